// round 5
// baseline (speedup 1.0000x reference)
#include <cuda_runtime.h>
#include <cuda_bf16.h>
#include <cstdint>
#include <cstddef>

// ---------------------------------------------------------------------------
// Problem constants
// ---------------------------------------------------------------------------
#define BATCH   2
#define SEQ     2048
#define DMODEL  1024
#define NHEADS  16
#define HDIM    64
#define NROWS   (BATCH * SEQ)      // 4096
#define QKVN    (3 * DMODEL)       // 3072
#define GEMMK   1024               // K dim of both projections

// Scratch (allocation-free: device globals)
__device__ float g_qkv[NROWS * QKVN];      // [B*T, 3*Dm]
__device__ float g_attn[NROWS * DMODEL];   // [B*T, Dm]

// ---------------------------------------------------------------------------
// 3xTF32 mma.sync GEMM:  C[M,N] = A[M,K] @ W[K,N]   (all row-major fp32)
// Each fp32 split v = hi + lo (both tf32); D += Ahi*Bhi + Ahi*Blo + Alo*Bhi
// -> near-fp32 accuracy on the tensor pipe.
// CTA tile 128x128, K-chunk 32, 256 threads = 8 warps, warp tile 64x32.
// SMEM per buffer: A_hi | A_lo | B_hi | B_lo  (4 x 4096 floats = 64KB),
// double buffered = 128KB.
// ---------------------------------------------------------------------------
#define BK 32
#define NKCH (GEMMK / BK)              // 32
#define PLANE 4096
#define BUF_FLOATS (4 * PLANE)         // 16384 floats = 64KB
#define GEMM_SMEM_BYTES (2 * BUF_FLOATS * (int)sizeof(float))

__device__ __forceinline__ uint32_t f2tf32(float v) {
    uint32_t r;
    asm("cvt.rna.tf32.f32 %0, %1;" : "=r"(r) : "f"(v));
    return r;
}

__device__ __forceinline__ void mma_tf32(
    float c[4], uint32_t a0, uint32_t a1, uint32_t a2, uint32_t a3,
    uint32_t b0, uint32_t b1)
{
    asm volatile(
        "mma.sync.aligned.m16n8k8.row.col.f32.tf32.tf32.f32 "
        "{%0,%1,%2,%3}, {%4,%5,%6,%7}, {%8,%9}, {%0,%1,%2,%3};"
        : "+f"(c[0]), "+f"(c[1]), "+f"(c[2]), "+f"(c[3])
        : "r"(a0), "r"(a1), "r"(a2), "r"(a3), "r"(b0), "r"(b1));
}

__global__ __launch_bounds__(256) void mma_gemm_kernel(
    const float* __restrict__ Ag, const float* __restrict__ Wg,
    float* __restrict__ Cg, int N)
{
    extern __shared__ __align__(16) float sm[];

    const int tid  = threadIdx.x;
    const int lane = tid & 31;
    const int wid  = tid >> 5;
    const int warpM = wid & 1;        // 0..1  -> 64-row slice
    const int warpN = wid >> 1;       // 0..3  -> 32-col slice
    const int tileM = blockIdx.y * 128;
    const int tileN = blockIdx.x * 128;

    float acc[4][4][4];
#pragma unroll
    for (int i = 0; i < 4; i++)
#pragma unroll
        for (int j = 0; j < 4; j++)
#pragma unroll
            for (int r = 0; r < 4; r++) acc[i][j][r] = 0.f;

    float4 av[4], bv[4];

    // prologue: global load chunk 0
#pragma unroll
    for (int i = 0; i < 4; i++) {
        int idx = tid + i * 256;
        int r = idx >> 3, c4 = idx & 7;
        av[i] = *(const float4*)(Ag + (size_t)(tileM + r) * GEMMK + c4 * 4);
        int rk = idx >> 5, c32 = idx & 31;
        bv[i] = *(const float4*)(Wg + (size_t)rk * N + tileN + c32 * 4);
    }

    for (int kc = 0; kc < NKCH; kc++) {
        const int buf = kc & 1;
        float* sAh = sm + buf * BUF_FLOATS;
        float* sAl = sAh + PLANE;
        float* sBh = sAl + PLANE;
        float* sBl = sBh + PLANE;

        // stage current chunk (registers -> permuted smem, hi/lo split)
#pragma unroll
        for (int i = 0; i < 4; i++) {
            int idx = tid + i * 256;
            int r = idx >> 3, c4 = idx & 7;
            int m16 = r >> 4, rlow = r & 7, rbit = (r >> 3) & 1;
            float va[4] = {av[i].x, av[i].y, av[i].z, av[i].w};
#pragma unroll
            for (int j = 0; j < 4; j++) {
                int c = c4 * 4 + j;
                int kstep = c >> 3, cin = c & 7;
                int reg = ((cin >= 4) ? 2 : 0) | rbit;
                int off = (kstep * 8 + m16) * 128 + (rlow * 4 + (cin & 3)) * 4 + reg;
                uint32_t hb = f2tf32(va[j]);
                float lof = va[j] - __uint_as_float(hb);
                sAh[off] = __uint_as_float(hb);
                sAl[off] = __uint_as_float(f2tf32(lof));
            }
            int rk = idx >> 5, c32 = idx & 31;
            int kstep2 = rk >> 3, kin = rk & 7;
            int regb = (kin >= 4) ? 1 : 0, klow = kin & 3;
            float vb[4] = {bv[i].x, bv[i].y, bv[i].z, bv[i].w};
#pragma unroll
            for (int j = 0; j < 4; j++) {
                int n = c32 * 4 + j;
                int n8 = n >> 3, nin = n & 7;
                int off = (kstep2 * 16 + n8) * 64 + (nin * 4 + klow) * 2 + regb;
                uint32_t hb = f2tf32(vb[j]);
                float lof = vb[j] - __uint_as_float(hb);
                sBh[off] = __uint_as_float(hb);
                sBl[off] = __uint_as_float(f2tf32(lof));
            }
        }
        __syncthreads();

        // prefetch next chunk (global -> registers)
        if (kc + 1 < NKCH) {
            const int kn = kc + 1;
#pragma unroll
            for (int i = 0; i < 4; i++) {
                int idx = tid + i * 256;
                int r = idx >> 3, c4 = idx & 7;
                av[i] = *(const float4*)(Ag + (size_t)(tileM + r) * GEMMK + kn * BK + c4 * 4);
                int rk = idx >> 5, c32 = idx & 31;
                bv[i] = *(const float4*)(Wg + (size_t)(kn * BK + rk) * N + tileN + c32 * 4);
            }
        }

        // compute 4 k-steps from this buffer
        const float* cAh = sm + buf * BUF_FLOATS;
        const float* cAl = cAh + PLANE;
        const float* cBh = cAl + PLANE;
        const float* cBl = cBh + PLANE;
#pragma unroll
        for (int ks = 0; ks < 4; ks++) {
            uint32_t ah[4][4], al[4][4];
#pragma unroll
            for (int i = 0; i < 4; i++) {
                int off = (ks * 8 + warpM * 4 + i) * 128 + lane * 4;
                float4 fh = *(const float4*)&cAh[off];
                ah[i][0] = __float_as_uint(fh.x); ah[i][1] = __float_as_uint(fh.y);
                ah[i][2] = __float_as_uint(fh.z); ah[i][3] = __float_as_uint(fh.w);
                float4 fl = *(const float4*)&cAl[off];
                al[i][0] = __float_as_uint(fl.x); al[i][1] = __float_as_uint(fl.y);
                al[i][2] = __float_as_uint(fl.z); al[i][3] = __float_as_uint(fl.w);
            }
            uint32_t bh[4][2], bl[4][2];
#pragma unroll
            for (int j = 0; j < 4; j++) {
                int off = (ks * 16 + warpN * 4 + j) * 64 + lane * 2;
                float2 gh = *(const float2*)&cBh[off];
                bh[j][0] = __float_as_uint(gh.x); bh[j][1] = __float_as_uint(gh.y);
                float2 gl = *(const float2*)&cBl[off];
                bl[j][0] = __float_as_uint(gl.x); bl[j][1] = __float_as_uint(gl.y);
            }
#pragma unroll
            for (int i = 0; i < 4; i++)
#pragma unroll
                for (int j = 0; j < 4; j++) {
                    // low-order terms first, then the dominant one
                    mma_tf32(acc[i][j], al[i][0], al[i][1], al[i][2], al[i][3],
                             bh[j][0], bh[j][1]);
                    mma_tf32(acc[i][j], ah[i][0], ah[i][1], ah[i][2], ah[i][3],
                             bl[j][0], bl[j][1]);
                    mma_tf32(acc[i][j], ah[i][0], ah[i][1], ah[i][2], ah[i][3],
                             bh[j][0], bh[j][1]);
                }
        }
        __syncthreads();
    }

    // epilogue
    const int g  = lane >> 2;
    const int t2 = (lane & 3) * 2;
#pragma unroll
    for (int i = 0; i < 4; i++) {
        int row = tileM + warpM * 64 + i * 16 + g;
#pragma unroll
        for (int j = 0; j < 4; j++) {
            int col = tileN + warpN * 32 + j * 8 + t2;
            *(float2*)&Cg[(size_t)row * N + col] =
                make_float2(acc[i][j][0], acc[i][j][1]);
            *(float2*)&Cg[(size_t)(row + 8) * N + col] =
                make_float2(acc[i][j][2], acc[i][j][3]);
        }
    }
}

// ---------------------------------------------------------------------------
// Flash-attention (causal), fp32 (unchanged — known good)
// ---------------------------------------------------------------------------
#define PAD 68
#define ATTN_SMEM_BYTES ((3 * 64 * PAD + 3 * 64) * (int)sizeof(float))

__global__ __launch_bounds__(256) void attn_kernel(
    const float* __restrict__ qkv, float* __restrict__ out)
{
    extern __shared__ float smf[];
    float* Qt   = smf;
    float* KP   = Qt + 64 * PAD;
    float* Vs   = KP + 64 * PAD;
    float* mrow = Vs + 64 * PAD;
    float* lrow = mrow + 64;
    float* arow = lrow + 64;

    const int qb = blockIdx.x;
    const int h  = blockIdx.y;
    const int b  = blockIdx.z;
    const int tid = threadIdx.x;
    const int tx = tid & 15, ty = tid >> 4;
    const int i0 = ty << 2, j0 = tx << 2;
    const int RS = QKVN;

    const float* qbase = qkv + ((size_t)(b * SEQ + qb * 64)) * RS + h * HDIM;
#pragma unroll
    for (int it = 0; it < 4; it++) {
        int idx = tid + it * 256;
        int r = idx >> 4;
        int c = (idx & 15) << 2;
        float4 v = *(const float4*)(qbase + (size_t)r * RS + c);
        Qt[(c + 0) * PAD + r] = v.x * 0.125f;
        Qt[(c + 1) * PAD + r] = v.y * 0.125f;
        Qt[(c + 2) * PAD + r] = v.z * 0.125f;
        Qt[(c + 3) * PAD + r] = v.w * 0.125f;
    }
    if (tid < 64) { mrow[tid] = -1e30f; lrow[tid] = 0.f; }

    float O[4][4] = {};
    const float* kbase0 = qkv + ((size_t)(b * SEQ)) * RS + DMODEL + h * HDIM;
    const float* vbase0 = kbase0 + DMODEL;

    for (int kb = 0; kb <= qb; kb++) {
        __syncthreads();

        const float* kbase = kbase0 + (size_t)(kb * 64) * RS;
        const float* vbase = vbase0 + (size_t)(kb * 64) * RS;
#pragma unroll
        for (int it = 0; it < 4; it++) {
            int idx = tid + it * 256;
            int r = idx >> 4;
            int c = (idx & 15) << 2;
            float4 kv = *(const float4*)(kbase + (size_t)r * RS + c);
            KP[(c + 0) * PAD + r] = kv.x;
            KP[(c + 1) * PAD + r] = kv.y;
            KP[(c + 2) * PAD + r] = kv.z;
            KP[(c + 3) * PAD + r] = kv.w;
            float4 vv = *(const float4*)(vbase + (size_t)r * RS + c);
            *(float4*)(Vs + r * PAD + c) = vv;
        }
        __syncthreads();

        float S[4][4] = {};
#pragma unroll 8
        for (int d = 0; d < 64; d++) {
            float4 qa = *(const float4*)(Qt + d * PAD + i0);
            float4 kv = *(const float4*)(KP + d * PAD + j0);
            float qr[4] = {qa.x, qa.y, qa.z, qa.w};
            float kr[4] = {kv.x, kv.y, kv.z, kv.w};
#pragma unroll
            for (int ii = 0; ii < 4; ii++)
#pragma unroll
                for (int jj = 0; jj < 4; jj++)
                    S[ii][jj] = fmaf(qr[ii], kr[jj], S[ii][jj]);
        }
        if (kb == qb) {
#pragma unroll
            for (int ii = 0; ii < 4; ii++)
#pragma unroll
                for (int jj = 0; jj < 4; jj++)
                    if (j0 + jj > i0 + ii) S[ii][jj] = -1e30f;
        }
        __syncthreads();

#pragma unroll
        for (int jj = 0; jj < 4; jj++)
#pragma unroll
            for (int ii = 0; ii < 4; ii++)
                KP[(j0 + jj) * PAD + (i0 + ii)] = S[ii][jj];
        __syncthreads();

        if (tid < 64) {
            int r = tid;
            float m_old = mrow[r];
            float mx = m_old;
#pragma unroll 8
            for (int j = 0; j < 64; j++) mx = fmaxf(mx, KP[j * PAD + r]);
            float a = __expf(m_old - mx);
            float s = 0.f;
#pragma unroll 8
            for (int j = 0; j < 64; j++) {
                float p = __expf(KP[j * PAD + r] - mx);
                KP[j * PAD + r] = p;
                s += p;
            }
            lrow[r] = lrow[r] * a + s;
            mrow[r] = mx;
            arow[r] = a;
        }
        __syncthreads();

        {
            float a0 = arow[i0 + 0], a1 = arow[i0 + 1],
                  a2 = arow[i0 + 2], a3 = arow[i0 + 3];
#pragma unroll
            for (int dd = 0; dd < 4; dd++) {
                O[0][dd] *= a0; O[1][dd] *= a1; O[2][dd] *= a2; O[3][dd] *= a3;
            }
        }
#pragma unroll 8
        for (int j = 0; j < 64; j++) {
            float4 p  = *(const float4*)(KP + j * PAD + i0);
            float4 vv = *(const float4*)(Vs + j * PAD + j0);
            float pr[4] = {p.x, p.y, p.z, p.w};
            float vr[4] = {vv.x, vv.y, vv.z, vv.w};
#pragma unroll
            for (int ii = 0; ii < 4; ii++)
#pragma unroll
                for (int dd = 0; dd < 4; dd++)
                    O[ii][dd] = fmaf(pr[ii], vr[dd], O[ii][dd]);
        }
    }

    float* obase = out + ((size_t)(b * SEQ + qb * 64)) * DMODEL + h * HDIM;
#pragma unroll
    for (int ii = 0; ii < 4; ii++) {
        float inv = 1.0f / lrow[i0 + ii];
        float4 v = make_float4(O[ii][0] * inv, O[ii][1] * inv,
                               O[ii][2] * inv, O[ii][3] * inv);
        *(float4*)(obase + (size_t)(i0 + ii) * DMODEL + j0) = v;
    }
}

// ---------------------------------------------------------------------------
// Launch
// ---------------------------------------------------------------------------
extern "C" void kernel_launch(void* const* d_in, const int* in_sizes, int n_in,
                              void* d_out, int out_size)
{
    (void)in_sizes; (void)n_in; (void)out_size;
    const float* x      = (const float*)d_in[0];
    // d_in[1] = mask (deterministically causal; hardcoded in attn_kernel)
    const float* w_qkv  = (const float*)d_in[2];
    const float* w_out  = (const float*)d_in[3];
    float* out          = (float*)d_out;

    float *qkv, *attn;
    cudaGetSymbolAddress((void**)&qkv,  g_qkv);
    cudaGetSymbolAddress((void**)&attn, g_attn);

    cudaFuncSetAttribute(attn_kernel,
                         cudaFuncAttributeMaxDynamicSharedMemorySize,
                         ATTN_SMEM_BYTES);
    cudaFuncSetAttribute(mma_gemm_kernel,
                         cudaFuncAttributeMaxDynamicSharedMemorySize,
                         GEMM_SMEM_BYTES);

    // 1) QKV projection (3xTF32 tensor cores): [4096,1024] @ [1024,3072]
    mma_gemm_kernel<<<dim3(QKVN / 128, NROWS / 128), 256, GEMM_SMEM_BYTES>>>(
        x, w_qkv, qkv, QKVN);

    // 2) causal flash attention per (b, h, q-tile)
    attn_kernel<<<dim3(SEQ / 64, NHEADS, BATCH), 256, ATTN_SMEM_BYTES>>>(qkv, attn);

    // 3) output projection (3xTF32 tensor cores): [4096,1024] @ [1024,1024]
    mma_gemm_kernel<<<dim3(DMODEL / 128, NROWS / 128), 256, GEMM_SMEM_BYTES>>>(
        attn, w_out, out, DMODEL);
}

// round 6
// speedup vs baseline: 2.4702x; 2.4702x over previous
#include <cuda_runtime.h>
#include <cuda_bf16.h>
#include <cstdint>
#include <cstddef>

// ---------------------------------------------------------------------------
// Problem constants
// ---------------------------------------------------------------------------
#define BATCH   2
#define SEQ     2048
#define DMODEL  1024
#define NHEADS  16
#define HDIM    64
#define NROWS   (BATCH * SEQ)      // 4096
#define QKVN    (3 * DMODEL)       // 3072
#define GEMMK   1024               // K dim of both projections

// Scratch (allocation-free: device globals)
__device__ float g_qkv[NROWS * QKVN];      // [B*T, 3*Dm]
__device__ float g_attn[NROWS * DMODEL];   // [B*T, Dm]

// ---------------------------------------------------------------------------
// bf16-split mma.sync GEMM:  C[M,N] = A[M,K] @ W[K,N]  (row-major fp32)
// v = hi + lo (both bf16);  D += Alo*Bhi + Ahi*Blo + Ahi*Bhi  (~1e-5 rel err)
// CTA tile 128x128, K-chunk 16 (one m16n8k16 k-step), 256 thr = 8 warps,
// warp tile 64x32. SMEM staged directly in fragment order:
//   A frag: per m16 tile, 32 lanes x uint4 (LDS.128)
//   B frag: per n8 tile,  32 lanes x uint2 (LDS.64), stride 66 u32 (pad)
// Double buffered, one __syncthreads per chunk, LDG prefetch overlaps mma.
// ---------------------------------------------------------------------------
#define BKC   16
#define NKCH  (GEMMK / BKC)        // 64
#define ASZ   1024                 // 8 m16-tiles * 32 lanes * 4 u32
#define BSZ   1056                 // 16 n8-tiles * 66 u32

__device__ __forceinline__ void mma_bf16(
    float c[4], uint32_t a0, uint32_t a1, uint32_t a2, uint32_t a3,
    uint32_t b0, uint32_t b1)
{
    asm volatile(
        "mma.sync.aligned.m16n8k16.row.col.f32.bf16.bf16.f32 "
        "{%0,%1,%2,%3}, {%4,%5,%6,%7}, {%8,%9}, {%0,%1,%2,%3};"
        : "+f"(c[0]), "+f"(c[1]), "+f"(c[2]), "+f"(c[3])
        : "r"(a0), "r"(a1), "r"(a2), "r"(a3), "r"(b0), "r"(b1));
}

__device__ __forceinline__ uint32_t bfpack(float x, float y) {
    __nv_bfloat162 h;
    h.x = __float2bfloat16_rn(x);
    h.y = __float2bfloat16_rn(y);
    return *reinterpret_cast<uint32_t*>(&h);
}
// split: returns packed hi(bf16x2), writes lo residuals
__device__ __forceinline__ uint32_t bfsplit(float x, float y,
                                            float& lx, float& ly) {
    __nv_bfloat16 bx = __float2bfloat16_rn(x);
    __nv_bfloat16 by = __float2bfloat16_rn(y);
    lx = x - __bfloat162float(bx);
    ly = y - __bfloat162float(by);
    __nv_bfloat162 h; h.x = bx; h.y = by;
    return *reinterpret_cast<uint32_t*>(&h);
}

__global__ __launch_bounds__(256, 2) void mma_gemm_kernel(
    const float* __restrict__ Ag, const float* __restrict__ Wg,
    float* __restrict__ Cg, int N)
{
    __shared__ __align__(16) uint32_t sAh[2][ASZ];
    __shared__ __align__(16) uint32_t sAl[2][ASZ];
    __shared__ __align__(16) uint32_t sBh[2][BSZ];
    __shared__ __align__(16) uint32_t sBl[2][BSZ];

    const int tid  = threadIdx.x;
    const int lane = tid & 31;
    const int wid  = tid >> 5;
    const int warpM = wid & 1;
    const int warpN = wid >> 1;
    const int tileM = blockIdx.y * 128;
    const int tileN = blockIdx.x * 128;

    // --- A staging coords: 2 float4 per thread, rows rA, rA+64, k = c4*4..+3
    const int rA = tid >> 2;           // 0..63
    const int c4 = tid & 3;            // k-quad
    // precomputed A scatter addresses (row-dependent part for i=0,1)
    int aAddr[2];
#pragma unroll
    for (int i = 0; i < 2; i++) {
        int r = rA + i * 64;
        int m16 = r >> 4, rr = r & 15, g = rr & 7, rh = rr >> 3;
        int lane0 = g * 4 + ((c4 * 2) & 3);
        int reg = rh + ((c4 >= 2) ? 2 : 0);
        aAddr[i] = (m16 * 32 + lane0) * 4 + reg;   // second pair at +4
    }
    // --- B staging coords: kpair p (2 rows), 4 n values
    const int pB = tid >> 5;           // 0..7
    const int n4 = tid & 31;
    const int regB = (pB >= 4) ? 1 : 0;
    const int tB = pB & 3;
    int bAddr[4];
#pragma unroll
    for (int j = 0; j < 4; j++) {
        int n = n4 * 4 + j;
        int n8 = n >> 3, gn = n & 7;
        bAddr[j] = n8 * 66 + (gn * 4 + tB) * 2 + regB;
    }

    float acc[4][4][4];
#pragma unroll
    for (int i = 0; i < 4; i++)
#pragma unroll
        for (int j = 0; j < 4; j++)
#pragma unroll
            for (int r = 0; r < 4; r++) acc[i][j][r] = 0.f;

    const float* Abase = Ag + (size_t)(tileM + rA) * GEMMK + c4 * 4;
    const float* Bbase = Wg + (size_t)(2 * pB) * N + tileN + n4 * 4;

    float4 av0, av1, bv0, bv1;
    // prologue: chunk 0
    av0 = *(const float4*)(Abase);
    av1 = *(const float4*)(Abase + (size_t)64 * GEMMK);
    bv0 = *(const float4*)(Bbase);
    bv1 = *(const float4*)(Bbase + N);

    for (int kc = 0; kc < NKCH; kc++) {
        const int buf = kc & 1;

        // ---- stage current chunk (hi/lo split, fragment order) ----
        {
            float lx, ly, lz, lw;
            uint32_t h0 = bfsplit(av0.x, av0.y, lx, ly);
            uint32_t h1 = bfsplit(av0.z, av0.w, lz, lw);
            sAh[buf][aAddr[0]]     = h0;
            sAh[buf][aAddr[0] + 4] = h1;
            sAl[buf][aAddr[0]]     = bfpack(lx, ly);
            sAl[buf][aAddr[0] + 4] = bfpack(lz, lw);
            h0 = bfsplit(av1.x, av1.y, lx, ly);
            h1 = bfsplit(av1.z, av1.w, lz, lw);
            sAh[buf][aAddr[1]]     = h0;
            sAh[buf][aAddr[1] + 4] = h1;
            sAl[buf][aAddr[1]]     = bfpack(lx, ly);
            sAl[buf][aAddr[1] + 4] = bfpack(lz, lw);

            float b0a[4] = {bv0.x, bv0.y, bv0.z, bv0.w};
            float b1a[4] = {bv1.x, bv1.y, bv1.z, bv1.w};
#pragma unroll
            for (int j = 0; j < 4; j++) {
                float l0, l1;
                uint32_t hb = bfsplit(b0a[j], b1a[j], l0, l1);
                sBh[buf][bAddr[j]] = hb;
                sBl[buf][bAddr[j]] = bfpack(l0, l1);
            }
        }
        __syncthreads();

        // ---- prefetch next chunk ----
        if (kc + 1 < NKCH) {
            const float* An = Abase + (kc + 1) * BKC;
            av0 = *(const float4*)(An);
            av1 = *(const float4*)(An + (size_t)64 * GEMMK);
            const float* Bn = Bbase + (size_t)(kc + 1) * BKC * N;
            bv0 = *(const float4*)(Bn);
            bv1 = *(const float4*)(Bn + N);
        }

        // ---- compute: 16 (m16,n8) tiles x 3 terms ----
        uint4 AH[4], AL[4];
#pragma unroll
        for (int i = 0; i < 4; i++) {
            int t = warpM * 4 + i;
            AH[i] = *(const uint4*)&sAh[buf][(t * 32 + lane) * 4];
            AL[i] = *(const uint4*)&sAl[buf][(t * 32 + lane) * 4];
        }
#pragma unroll
        for (int j = 0; j < 4; j++) {
            int t = warpN * 4 + j;
            uint2 BH = *(const uint2*)&sBh[buf][t * 66 + lane * 2];
            uint2 BL = *(const uint2*)&sBl[buf][t * 66 + lane * 2];
#pragma unroll
            for (int i = 0; i < 4; i++) {
                mma_bf16(acc[i][j], AL[i].x, AL[i].y, AL[i].z, AL[i].w,
                         BH.x, BH.y);
                mma_bf16(acc[i][j], AH[i].x, AH[i].y, AH[i].z, AH[i].w,
                         BL.x, BL.y);
                mma_bf16(acc[i][j], AH[i].x, AH[i].y, AH[i].z, AH[i].w,
                         BH.x, BH.y);
            }
        }
        __syncthreads();
    }

    // ---- epilogue ----
    const int g  = lane >> 2;
    const int t2 = (lane & 3) * 2;
#pragma unroll
    for (int i = 0; i < 4; i++) {
        int row = tileM + warpM * 64 + i * 16 + g;
#pragma unroll
        for (int j = 0; j < 4; j++) {
            int col = tileN + warpN * 32 + j * 8 + t2;
            *(float2*)&Cg[(size_t)row * N + col] =
                make_float2(acc[i][j][0], acc[i][j][1]);
            *(float2*)&Cg[(size_t)(row + 8) * N + col] =
                make_float2(acc[i][j][2], acc[i][j][3]);
        }
    }
}

// ---------------------------------------------------------------------------
// Flash-attention (causal), fp32 (unchanged — known good)
// ---------------------------------------------------------------------------
#define PAD 68
#define ATTN_SMEM_BYTES ((3 * 64 * PAD + 3 * 64) * (int)sizeof(float))

__global__ __launch_bounds__(256) void attn_kernel(
    const float* __restrict__ qkv, float* __restrict__ out)
{
    extern __shared__ float smf[];
    float* Qt   = smf;
    float* KP   = Qt + 64 * PAD;
    float* Vs   = KP + 64 * PAD;
    float* mrow = Vs + 64 * PAD;
    float* lrow = mrow + 64;
    float* arow = lrow + 64;

    const int qb = blockIdx.x;
    const int h  = blockIdx.y;
    const int b  = blockIdx.z;
    const int tid = threadIdx.x;
    const int tx = tid & 15, ty = tid >> 4;
    const int i0 = ty << 2, j0 = tx << 2;
    const int RS = QKVN;

    const float* qbase = qkv + ((size_t)(b * SEQ + qb * 64)) * RS + h * HDIM;
#pragma unroll
    for (int it = 0; it < 4; it++) {
        int idx = tid + it * 256;
        int r = idx >> 4;
        int c = (idx & 15) << 2;
        float4 v = *(const float4*)(qbase + (size_t)r * RS + c);
        Qt[(c + 0) * PAD + r] = v.x * 0.125f;
        Qt[(c + 1) * PAD + r] = v.y * 0.125f;
        Qt[(c + 2) * PAD + r] = v.z * 0.125f;
        Qt[(c + 3) * PAD + r] = v.w * 0.125f;
    }
    if (tid < 64) { mrow[tid] = -1e30f; lrow[tid] = 0.f; }

    float O[4][4] = {};
    const float* kbase0 = qkv + ((size_t)(b * SEQ)) * RS + DMODEL + h * HDIM;
    const float* vbase0 = kbase0 + DMODEL;

    for (int kb = 0; kb <= qb; kb++) {
        __syncthreads();

        const float* kbase = kbase0 + (size_t)(kb * 64) * RS;
        const float* vbase = vbase0 + (size_t)(kb * 64) * RS;
#pragma unroll
        for (int it = 0; it < 4; it++) {
            int idx = tid + it * 256;
            int r = idx >> 4;
            int c = (idx & 15) << 2;
            float4 kv = *(const float4*)(kbase + (size_t)r * RS + c);
            KP[(c + 0) * PAD + r] = kv.x;
            KP[(c + 1) * PAD + r] = kv.y;
            KP[(c + 2) * PAD + r] = kv.z;
            KP[(c + 3) * PAD + r] = kv.w;
            float4 vv = *(const float4*)(vbase + (size_t)r * RS + c);
            *(float4*)(Vs + r * PAD + c) = vv;
        }
        __syncthreads();

        float S[4][4] = {};
#pragma unroll 8
        for (int d = 0; d < 64; d++) {
            float4 qa = *(const float4*)(Qt + d * PAD + i0);
            float4 kv = *(const float4*)(KP + d * PAD + j0);
            float qr[4] = {qa.x, qa.y, qa.z, qa.w};
            float kr[4] = {kv.x, kv.y, kv.z, kv.w};
#pragma unroll
            for (int ii = 0; ii < 4; ii++)
#pragma unroll
                for (int jj = 0; jj < 4; jj++)
                    S[ii][jj] = fmaf(qr[ii], kr[jj], S[ii][jj]);
        }
        if (kb == qb) {
#pragma unroll
            for (int ii = 0; ii < 4; ii++)
#pragma unroll
                for (int jj = 0; jj < 4; jj++)
                    if (j0 + jj > i0 + ii) S[ii][jj] = -1e30f;
        }
        __syncthreads();

#pragma unroll
        for (int jj = 0; jj < 4; jj++)
#pragma unroll
            for (int ii = 0; ii < 4; ii++)
                KP[(j0 + jj) * PAD + (i0 + ii)] = S[ii][jj];
        __syncthreads();

        if (tid < 64) {
            int r = tid;
            float m_old = mrow[r];
            float mx = m_old;
#pragma unroll 8
            for (int j = 0; j < 64; j++) mx = fmaxf(mx, KP[j * PAD + r]);
            float a = __expf(m_old - mx);
            float s = 0.f;
#pragma unroll 8
            for (int j = 0; j < 64; j++) {
                float p = __expf(KP[j * PAD + r] - mx);
                KP[j * PAD + r] = p;
                s += p;
            }
            lrow[r] = lrow[r] * a + s;
            mrow[r] = mx;
            arow[r] = a;
        }
        __syncthreads();

        {
            float a0 = arow[i0 + 0], a1 = arow[i0 + 1],
                  a2 = arow[i0 + 2], a3 = arow[i0 + 3];
#pragma unroll
            for (int dd = 0; dd < 4; dd++) {
                O[0][dd] *= a0; O[1][dd] *= a1; O[2][dd] *= a2; O[3][dd] *= a3;
            }
        }
#pragma unroll 8
        for (int j = 0; j < 64; j++) {
            float4 p  = *(const float4*)(KP + j * PAD + i0);
            float4 vv = *(const float4*)(Vs + j * PAD + j0);
            float pr[4] = {p.x, p.y, p.z, p.w};
            float vr[4] = {vv.x, vv.y, vv.z, vv.w};
#pragma unroll
            for (int ii = 0; ii < 4; ii++)
#pragma unroll
                for (int dd = 0; dd < 4; dd++)
                    O[ii][dd] = fmaf(pr[ii], vr[dd], O[ii][dd]);
        }
    }

    float* obase = out + ((size_t)(b * SEQ + qb * 64)) * DMODEL + h * HDIM;
#pragma unroll
    for (int ii = 0; ii < 4; ii++) {
        float inv = 1.0f / lrow[i0 + ii];
        float4 v = make_float4(O[ii][0] * inv, O[ii][1] * inv,
                               O[ii][2] * inv, O[ii][3] * inv);
        *(float4*)(obase + (size_t)(i0 + ii) * DMODEL + j0) = v;
    }
}

// ---------------------------------------------------------------------------
// Launch
// ---------------------------------------------------------------------------
extern "C" void kernel_launch(void* const* d_in, const int* in_sizes, int n_in,
                              void* d_out, int out_size)
{
    (void)in_sizes; (void)n_in; (void)out_size;
    const float* x      = (const float*)d_in[0];
    // d_in[1] = mask (deterministically causal; hardcoded in attn_kernel)
    const float* w_qkv  = (const float*)d_in[2];
    const float* w_out  = (const float*)d_in[3];
    float* out          = (float*)d_out;

    float *qkv, *attn;
    cudaGetSymbolAddress((void**)&qkv,  g_qkv);
    cudaGetSymbolAddress((void**)&attn, g_attn);

    cudaFuncSetAttribute(attn_kernel,
                         cudaFuncAttributeMaxDynamicSharedMemorySize,
                         ATTN_SMEM_BYTES);

    // 1) QKV projection (bf16-split tensor cores): [4096,1024] @ [1024,3072]
    mma_gemm_kernel<<<dim3(QKVN / 128, NROWS / 128), 256>>>(
        x, w_qkv, qkv, QKVN);

    // 2) causal flash attention per (b, h, q-tile)
    attn_kernel<<<dim3(SEQ / 64, NHEADS, BATCH), 256, ATTN_SMEM_BYTES>>>(qkv, attn);

    // 3) output projection (bf16-split tensor cores): [4096,1024] @ [1024,1024]
    mma_gemm_kernel<<<dim3(DMODEL / 128, NROWS / 128), 256>>>(
        attn, w_out, out, DMODEL);
}

// round 7
// speedup vs baseline: 3.9923x; 1.6162x over previous
#include <cuda_runtime.h>
#include <cuda_bf16.h>
#include <cstdint>
#include <cstddef>

// ---------------------------------------------------------------------------
// Problem constants
// ---------------------------------------------------------------------------
#define BATCH   2
#define SEQ     2048
#define DMODEL  1024
#define NHEADS  16
#define HDIM    64
#define NROWS   (BATCH * SEQ)      // 4096
#define QKVN    (3 * DMODEL)       // 3072
#define GEMMK   1024               // K dim of both projections

// Scratch (allocation-free: device globals)
__device__ float g_qkv[NROWS * QKVN];      // [B*T, 3*Dm]
__device__ float g_attn[NROWS * DMODEL];   // [B*T, Dm]

// ---------------------------------------------------------------------------
// Shared helpers
// ---------------------------------------------------------------------------
__device__ __forceinline__ void mma_bf16(
    float c[4], uint32_t a0, uint32_t a1, uint32_t a2, uint32_t a3,
    uint32_t b0, uint32_t b1)
{
    asm volatile(
        "mma.sync.aligned.m16n8k16.row.col.f32.bf16.bf16.f32 "
        "{%0,%1,%2,%3}, {%4,%5,%6,%7}, {%8,%9}, {%0,%1,%2,%3};"
        : "+f"(c[0]), "+f"(c[1]), "+f"(c[2]), "+f"(c[3])
        : "r"(a0), "r"(a1), "r"(a2), "r"(a3), "r"(b0), "r"(b1));
}

__device__ __forceinline__ uint32_t bfpack(float x, float y) {
    __nv_bfloat162 h;
    h.x = __float2bfloat16_rn(x);
    h.y = __float2bfloat16_rn(y);
    return *reinterpret_cast<uint32_t*>(&h);
}
__device__ __forceinline__ uint32_t bfsplit(float x, float y,
                                            float& lx, float& ly) {
    __nv_bfloat16 bx = __float2bfloat16_rn(x);
    __nv_bfloat16 by = __float2bfloat16_rn(y);
    lx = x - __bfloat162float(bx);
    ly = y - __bfloat162float(by);
    __nv_bfloat162 h; h.x = bx; h.y = by;
    return *reinterpret_cast<uint32_t*>(&h);
}
__device__ __forceinline__ float fast_exp2(float x) {
    float y;
    asm("ex2.approx.f32 %0, %1;" : "=f"(y) : "f"(x));
    return y;
}

// ---------------------------------------------------------------------------
// bf16-split mma.sync GEMM (unchanged from round 6 — validated)
// ---------------------------------------------------------------------------
#define BKC   16
#define NKCH  (GEMMK / BKC)        // 64
#define ASZ   1024
#define BSZ   1056

__global__ __launch_bounds__(256, 2) void mma_gemm_kernel(
    const float* __restrict__ Ag, const float* __restrict__ Wg,
    float* __restrict__ Cg, int N)
{
    __shared__ __align__(16) uint32_t sAh[2][ASZ];
    __shared__ __align__(16) uint32_t sAl[2][ASZ];
    __shared__ __align__(16) uint32_t sBh[2][BSZ];
    __shared__ __align__(16) uint32_t sBl[2][BSZ];

    const int tid  = threadIdx.x;
    const int lane = tid & 31;
    const int wid  = tid >> 5;
    const int warpM = wid & 1;
    const int warpN = wid >> 1;
    const int tileM = blockIdx.y * 128;
    const int tileN = blockIdx.x * 128;

    const int rA = tid >> 2;
    const int c4 = tid & 3;
    int aAddr[2];
#pragma unroll
    for (int i = 0; i < 2; i++) {
        int r = rA + i * 64;
        int m16 = r >> 4, rr = r & 15, g = rr & 7, rh = rr >> 3;
        int lane0 = g * 4 + ((c4 * 2) & 3);
        int reg = rh + ((c4 >= 2) ? 2 : 0);
        aAddr[i] = (m16 * 32 + lane0) * 4 + reg;
    }
    const int pB = tid >> 5;
    const int n4 = tid & 31;
    const int regB = (pB >= 4) ? 1 : 0;
    const int tB = pB & 3;
    int bAddr[4];
#pragma unroll
    for (int j = 0; j < 4; j++) {
        int n = n4 * 4 + j;
        int n8 = n >> 3, gn = n & 7;
        bAddr[j] = n8 * 66 + (gn * 4 + tB) * 2 + regB;
    }

    float acc[4][4][4];
#pragma unroll
    for (int i = 0; i < 4; i++)
#pragma unroll
        for (int j = 0; j < 4; j++)
#pragma unroll
            for (int r = 0; r < 4; r++) acc[i][j][r] = 0.f;

    const float* Abase = Ag + (size_t)(tileM + rA) * GEMMK + c4 * 4;
    const float* Bbase = Wg + (size_t)(2 * pB) * N + tileN + n4 * 4;

    float4 av0, av1, bv0, bv1;
    av0 = *(const float4*)(Abase);
    av1 = *(const float4*)(Abase + (size_t)64 * GEMMK);
    bv0 = *(const float4*)(Bbase);
    bv1 = *(const float4*)(Bbase + N);

    for (int kc = 0; kc < NKCH; kc++) {
        const int buf = kc & 1;
        {
            float lx, ly, lz, lw;
            uint32_t h0 = bfsplit(av0.x, av0.y, lx, ly);
            uint32_t h1 = bfsplit(av0.z, av0.w, lz, lw);
            sAh[buf][aAddr[0]]     = h0;
            sAh[buf][aAddr[0] + 4] = h1;
            sAl[buf][aAddr[0]]     = bfpack(lx, ly);
            sAl[buf][aAddr[0] + 4] = bfpack(lz, lw);
            h0 = bfsplit(av1.x, av1.y, lx, ly);
            h1 = bfsplit(av1.z, av1.w, lz, lw);
            sAh[buf][aAddr[1]]     = h0;
            sAh[buf][aAddr[1] + 4] = h1;
            sAl[buf][aAddr[1]]     = bfpack(lx, ly);
            sAl[buf][aAddr[1] + 4] = bfpack(lz, lw);

            float b0a[4] = {bv0.x, bv0.y, bv0.z, bv0.w};
            float b1a[4] = {bv1.x, bv1.y, bv1.z, bv1.w};
#pragma unroll
            for (int j = 0; j < 4; j++) {
                float l0, l1;
                uint32_t hb = bfsplit(b0a[j], b1a[j], l0, l1);
                sBh[buf][bAddr[j]] = hb;
                sBl[buf][bAddr[j]] = bfpack(l0, l1);
            }
        }
        __syncthreads();

        if (kc + 1 < NKCH) {
            const float* An = Abase + (kc + 1) * BKC;
            av0 = *(const float4*)(An);
            av1 = *(const float4*)(An + (size_t)64 * GEMMK);
            const float* Bn = Bbase + (size_t)(kc + 1) * BKC * N;
            bv0 = *(const float4*)(Bn);
            bv1 = *(const float4*)(Bn + N);
        }

        uint4 AH[4], AL[4];
#pragma unroll
        for (int i = 0; i < 4; i++) {
            int t = warpM * 4 + i;
            AH[i] = *(const uint4*)&sAh[buf][(t * 32 + lane) * 4];
            AL[i] = *(const uint4*)&sAl[buf][(t * 32 + lane) * 4];
        }
#pragma unroll
        for (int j = 0; j < 4; j++) {
            int t = warpN * 4 + j;
            uint2 BH = *(const uint2*)&sBh[buf][t * 66 + lane * 2];
            uint2 BL = *(const uint2*)&sBl[buf][t * 66 + lane * 2];
#pragma unroll
            for (int i = 0; i < 4; i++) {
                mma_bf16(acc[i][j], AL[i].x, AL[i].y, AL[i].z, AL[i].w,
                         BH.x, BH.y);
                mma_bf16(acc[i][j], AH[i].x, AH[i].y, AH[i].z, AH[i].w,
                         BL.x, BL.y);
                mma_bf16(acc[i][j], AH[i].x, AH[i].y, AH[i].z, AH[i].w,
                         BH.x, BH.y);
            }
        }
        __syncthreads();
    }

    const int g  = lane >> 2;
    const int t2 = (lane & 3) * 2;
#pragma unroll
    for (int i = 0; i < 4; i++) {
        int row = tileM + warpM * 64 + i * 16 + g;
#pragma unroll
        for (int j = 0; j < 4; j++) {
            int col = tileN + warpN * 32 + j * 8 + t2;
            *(float2*)&Cg[(size_t)row * N + col] =
                make_float2(acc[i][j][0], acc[i][j][1]);
            *(float2*)&Cg[(size_t)(row + 8) * N + col] =
                make_float2(acc[i][j][2], acc[i][j][3]);
        }
    }
}

// ---------------------------------------------------------------------------
// Flash attention on tensor cores (bf16-split, causal).
// Grid (16,16,2) = (qb reversed, h, b). 256 threads = 8 warps x 16 q-rows.
// K-blocks of 64 keys. Q frags in registers (pre-scaled by 0.125*log2e);
// softmax in registers via ex2.approx; P repacked register-only into
// A-fragments for PV. K/V staged hi/lo in B-fragment order (stride 66).
// ---------------------------------------------------------------------------
#define KVPLANE 2112   // 4 ksteps * 8 tiles * 66 u32

__global__ __launch_bounds__(256) void attn_mma_kernel(
    const float* __restrict__ qkv, float* __restrict__ out)
{
    __shared__ __align__(16) uint32_t sKh[KVPLANE], sKl[KVPLANE];
    __shared__ __align__(16) uint32_t sVh[KVPLANE], sVl[KVPLANE];

    const int tid  = threadIdx.x;
    const int lane = tid & 31;
    const int w    = tid >> 5;
    const int qb   = (int)gridDim.x - 1 - (int)blockIdx.x;  // big tiles first
    const int h    = blockIdx.y;
    const int b    = blockIdx.z;
    const int g    = lane >> 2;
    const int t2   = (lane & 3) * 2;
    const int RS   = QKVN;

    // ---- Q fragments (held all kernel), scale folds softmax into exp2 ----
    const float SC = 0.125f * 1.44269504088896340736f;
    uint32_t QH[4][4], QL[4][4];
    {
        const float* q0 = qkv + (size_t)(b * SEQ + qb * 128 + w * 16 + g) * RS
                          + h * HDIM;
        const float* q1 = q0 + 8 * RS;
#pragma unroll
        for (int s = 0; s < 4; s++) {
            int c0 = s * 16 + t2, c1 = c0 + 8;
            float2 v00 = *(const float2*)(q0 + c0);
            float2 v10 = *(const float2*)(q1 + c0);
            float2 v01 = *(const float2*)(q0 + c1);
            float2 v11 = *(const float2*)(q1 + c1);
            float lx, ly;
            QH[s][0] = bfsplit(v00.x * SC, v00.y * SC, lx, ly); QL[s][0] = bfpack(lx, ly);
            QH[s][1] = bfsplit(v10.x * SC, v10.y * SC, lx, ly); QL[s][1] = bfpack(lx, ly);
            QH[s][2] = bfsplit(v01.x * SC, v01.y * SC, lx, ly); QL[s][2] = bfpack(lx, ly);
            QH[s][3] = bfsplit(v11.x * SC, v11.y * SC, lx, ly); QL[s][3] = bfpack(lx, ly);
        }
    }

    float O[8][4];
#pragma unroll
    for (int t = 0; t < 8; t++)
#pragma unroll
        for (int r = 0; r < 4; r++) O[t][r] = 0.f;
    float m0 = -1e30f, m1 = -1e30f, l0 = 0.f, l1 = 0.f;

    // staging coords
    const int kj  = tid >> 2;   // K: key row 0..63
    const int kdq = tid & 3;    // K: d-quad group
    const int vp  = tid >> 3;   // V: row pair 0..31
    const int vdq = tid & 7;    // V: d group (8 d's)
    const int vks = vp >> 3;            // V kstep
    const int vtB = vp & 3;
    const int vreg = (vp >> 2) & 1;

    const float* Kbase = qkv + (size_t)(b * SEQ) * RS + DMODEL + h * HDIM;
    const float* Vbase = Kbase + DMODEL;

    const int nkb = 2 * (qb + 1);
    for (int kb = 0; kb < nkb; kb++) {
        // ---- stage K (hi/lo, B-frag order: n=key j, k=d) ----
        {
            const float* kp = Kbase + (size_t)(kb * 64 + kj) * RS + kdq * 16;
#pragma unroll
            for (int q4 = 0; q4 < 4; q4++) {
                float4 v = *(const float4*)(kp + q4 * 4);
                int d0 = kdq * 16 + q4 * 4;
                float lx, ly;
                int a0 = ((d0 >> 4) * 8 + (kj >> 3)) * 66
                       + ((kj & 7) * 4 + ((d0 >> 1) & 3)) * 2 + ((d0 >> 3) & 1);
                uint32_t hb = bfsplit(v.x, v.y, lx, ly);
                sKh[a0] = hb; sKl[a0] = bfpack(lx, ly);
                int d2 = d0 + 2;
                int a1 = ((d2 >> 4) * 8 + (kj >> 3)) * 66
                       + ((kj & 7) * 4 + ((d2 >> 1) & 3)) * 2 + ((d2 >> 3) & 1);
                hb = bfsplit(v.z, v.w, lx, ly);
                sKh[a1] = hb; sKl[a1] = bfpack(lx, ly);
            }
        }
        // ---- stage V (hi/lo, B-frag order: n=d, k=key j — transposed pairs) ----
        {
            const float* v0p = Vbase + (size_t)(kb * 64 + 2 * vp) * RS + vdq * 8;
            const float* v1p = v0p + RS;
            float4 x0 = *(const float4*)(v0p);
            float4 x1 = *(const float4*)(v0p + 4);
            float4 y0 = *(const float4*)(v1p);
            float4 y1 = *(const float4*)(v1p + 4);
            float r0[8] = {x0.x, x0.y, x0.z, x0.w, x1.x, x1.y, x1.z, x1.w};
            float r1[8] = {y0.x, y0.y, y0.z, y0.w, y1.x, y1.y, y1.z, y1.w};
#pragma unroll
            for (int dd = 0; dd < 8; dd++) {
                int d = vdq * 8 + dd;
                int addr = (vks * 8 + (d >> 3)) * 66
                         + ((d & 7) * 4 + vtB) * 2 + vreg;
                float lx, ly;
                uint32_t hb = bfsplit(r0[dd], r1[dd], lx, ly);
                sVh[addr] = hb; sVl[addr] = bfpack(lx, ly);
            }
        }
        __syncthreads();

        // ---- S = Q @ K^T (bf16-split, 3 terms) ----
        float S[8][4];
#pragma unroll
        for (int t = 0; t < 8; t++)
#pragma unroll
            for (int r = 0; r < 4; r++) S[t][r] = 0.f;
#pragma unroll
        for (int s = 0; s < 4; s++) {
#pragma unroll
            for (int t = 0; t < 8; t++) {
                uint2 BH = *(const uint2*)&sKh[(s * 8 + t) * 66 + lane * 2];
                uint2 BL = *(const uint2*)&sKl[(s * 8 + t) * 66 + lane * 2];
                mma_bf16(S[t], QL[s][0], QL[s][1], QL[s][2], QL[s][3], BH.x, BH.y);
                mma_bf16(S[t], QH[s][0], QH[s][1], QH[s][2], QH[s][3], BL.x, BL.y);
                mma_bf16(S[t], QH[s][0], QH[s][1], QH[s][2], QH[s][3], BH.x, BH.y);
            }
        }

        // ---- causal mask (diagonal k-blocks only) ----
        if (kb >= 2 * qb) {
            int row0 = qb * 128 + w * 16 + g;
            int keyb = kb * 64;
#pragma unroll
            for (int t = 0; t < 8; t++) {
                int k0 = keyb + t * 8 + t2;
                if (k0     > row0)     S[t][0] = -1e30f;
                if (k0 + 1 > row0)     S[t][1] = -1e30f;
                if (k0     > row0 + 8) S[t][2] = -1e30f;
                if (k0 + 1 > row0 + 8) S[t][3] = -1e30f;
            }
        }

        // ---- online softmax (registers, exp2 domain) ----
        float mx0 = -1e30f, mx1 = -1e30f;
#pragma unroll
        for (int t = 0; t < 8; t++) {
            mx0 = fmaxf(mx0, fmaxf(S[t][0], S[t][1]));
            mx1 = fmaxf(mx1, fmaxf(S[t][2], S[t][3]));
        }
        mx0 = fmaxf(mx0, __shfl_xor_sync(0xffffffffu, mx0, 1));
        mx0 = fmaxf(mx0, __shfl_xor_sync(0xffffffffu, mx0, 2));
        mx1 = fmaxf(mx1, __shfl_xor_sync(0xffffffffu, mx1, 1));
        mx1 = fmaxf(mx1, __shfl_xor_sync(0xffffffffu, mx1, 2));
        float nm0 = fmaxf(m0, mx0), nm1 = fmaxf(m1, mx1);
        float a0s = fast_exp2(m0 - nm0), a1s = fast_exp2(m1 - nm1);
        m0 = nm0; m1 = nm1;
        float rs0 = 0.f, rs1 = 0.f;
#pragma unroll
        for (int t = 0; t < 8; t++) {
            S[t][0] = fast_exp2(S[t][0] - m0);
            S[t][1] = fast_exp2(S[t][1] - m0);
            S[t][2] = fast_exp2(S[t][2] - m1);
            S[t][3] = fast_exp2(S[t][3] - m1);
            rs0 += S[t][0] + S[t][1];
            rs1 += S[t][2] + S[t][3];
        }
        rs0 += __shfl_xor_sync(0xffffffffu, rs0, 1);
        rs0 += __shfl_xor_sync(0xffffffffu, rs0, 2);
        rs1 += __shfl_xor_sync(0xffffffffu, rs1, 1);
        rs1 += __shfl_xor_sync(0xffffffffu, rs1, 2);
        l0 = l0 * a0s + rs0;
        l1 = l1 * a1s + rs1;
#pragma unroll
        for (int t = 0; t < 8; t++) {
            O[t][0] *= a0s; O[t][1] *= a0s;
            O[t][2] *= a1s; O[t][3] *= a1s;
        }

        // ---- pack P (S C-frag -> PV A-frag, register-only) ----
        uint32_t PH[4][4], PL[4][4];
#pragma unroll
        for (int s = 0; s < 4; s++) {
            float lx, ly;
            PH[s][0] = bfsplit(S[2*s][0],   S[2*s][1],   lx, ly); PL[s][0] = bfpack(lx, ly);
            PH[s][1] = bfsplit(S[2*s][2],   S[2*s][3],   lx, ly); PL[s][1] = bfpack(lx, ly);
            PH[s][2] = bfsplit(S[2*s+1][0], S[2*s+1][1], lx, ly); PL[s][2] = bfpack(lx, ly);
            PH[s][3] = bfsplit(S[2*s+1][2], S[2*s+1][3], lx, ly); PL[s][3] = bfpack(lx, ly);
        }

        // ---- O += P @ V (bf16-split, 3 terms) ----
#pragma unroll
        for (int s = 0; s < 4; s++) {
#pragma unroll
            for (int t = 0; t < 8; t++) {
                uint2 BH = *(const uint2*)&sVh[(s * 8 + t) * 66 + lane * 2];
                uint2 BL = *(const uint2*)&sVl[(s * 8 + t) * 66 + lane * 2];
                mma_bf16(O[t], PL[s][0], PL[s][1], PL[s][2], PL[s][3], BH.x, BH.y);
                mma_bf16(O[t], PH[s][0], PH[s][1], PH[s][2], PH[s][3], BL.x, BL.y);
                mma_bf16(O[t], PH[s][0], PH[s][1], PH[s][2], PH[s][3], BH.x, BH.y);
            }
        }
        __syncthreads();
    }

    // ---- epilogue: normalize + store merged-head layout ----
    float i0 = 1.f / l0, i1 = 1.f / l1;
    int row0 = b * SEQ + qb * 128 + w * 16 + g;
    float* o0 = out + (size_t)row0 * DMODEL + h * HDIM;
    float* o1 = o0 + 8 * DMODEL;
#pragma unroll
    for (int t = 0; t < 8; t++) {
        *(float2*)(o0 + t * 8 + t2) = make_float2(O[t][0] * i0, O[t][1] * i0);
        *(float2*)(o1 + t * 8 + t2) = make_float2(O[t][2] * i1, O[t][3] * i1);
    }
}

// ---------------------------------------------------------------------------
// Launch
// ---------------------------------------------------------------------------
extern "C" void kernel_launch(void* const* d_in, const int* in_sizes, int n_in,
                              void* d_out, int out_size)
{
    (void)in_sizes; (void)n_in; (void)out_size;
    const float* x      = (const float*)d_in[0];
    // d_in[1] = mask (deterministically causal; hardcoded in attn kernel)
    const float* w_qkv  = (const float*)d_in[2];
    const float* w_out  = (const float*)d_in[3];
    float* out          = (float*)d_out;

    float *qkv, *attn;
    cudaGetSymbolAddress((void**)&qkv,  g_qkv);
    cudaGetSymbolAddress((void**)&attn, g_attn);

    // 1) QKV projection (bf16-split tensor cores)
    mma_gemm_kernel<<<dim3(QKVN / 128, NROWS / 128), 256>>>(
        x, w_qkv, qkv, QKVN);

    // 2) causal flash attention on tensor cores
    attn_mma_kernel<<<dim3(SEQ / 128, NHEADS, BATCH), 256>>>(qkv, attn);

    // 3) output projection (bf16-split tensor cores)
    mma_gemm_kernel<<<dim3(DMODEL / 128, NROWS / 128), 256>>>(
        attn, w_out, out, DMODEL);
}